// round 2
// baseline (speedup 1.0000x reference)
#include <cuda_runtime.h>

// CategoricalProjection (C51 distributional RL projection)
// rows = 524288, NUM_ATOMS = 51
// inputs: d_in[0] = reward [rows], d_in[1] = probs [rows*51], d_in[2] = not_done [rows]
// output: new_probs [rows*51] float32

#define NUM_ATOMS 51
#define V_MINF (-10.0f)
#define V_MAXF (10.0f)
#define DISCOUNTF (0.99f)
#define THREADS 256
#define ROWS_PER_BLOCK 256

__global__ __launch_bounds__(THREADS, 2)
void c51_proj_kernel(const float* __restrict__ reward,
                     const float* __restrict__ probs,
                     const float* __restrict__ not_done,
                     float* __restrict__ out,
                     int rows)
{
    extern __shared__ float smem[];
    float* in_s  = smem;                                  // ROWS_PER_BLOCK * NUM_ATOMS
    float* out_s = smem + ROWS_PER_BLOCK * NUM_ATOMS;     // ROWS_PER_BLOCK * NUM_ATOMS

    const int tid = threadIdx.x;
    const long long tile_elems = (long long)ROWS_PER_BLOCK * NUM_ATOMS;
    const long long block_base = (long long)blockIdx.x * tile_elems;
    const long long total_elems = (long long)rows * NUM_ATOMS;

    // -------- cooperative coalesced load of the probs tile --------
    const float* gin = probs + block_base;
    #pragma unroll
    for (int i = 0; i < NUM_ATOMS; i++) {
        int idx = i * THREADS + tid;
        if (block_base + idx < total_elems) in_s[idx] = gin[idx];
    }
    __syncthreads();

    const int row = blockIdx.x * ROWS_PER_BLOCK + tid;

    if (row < rows) {
        const float r  = reward[row];
        const float nd = not_done[row];
        const float slope = DISCOUNTF * nd;                       // 0 or 0.99
        const float delta = (V_MAXF - V_MINF) / (float)(NUM_ATOMS - 1);  // 0.4
        const float inv_delta = 1.0f / delta;

        float* my_in  = in_s  + tid * NUM_ATOMS;
        float* my_out = out_s + tid * NUM_ATOMS;

        // first target bin: b_0 from atom z_0 = V_MIN
        float v0 = fminf(fmaxf(fmaf(slope, V_MINF, r), V_MINF), V_MAXF);
        int l0 = (int)floorf((v0 - V_MINF) * inv_delta);

        // zero-fill head bins [0, l0)
        for (int i = 0; i < l0; i++) my_out[i] = 0.0f;

        int cur = l0;
        float a0 = 0.0f, a1 = 0.0f;

        // streaming scatter: floor(b_j) is monotone, advances by <= 1 per atom
        #pragma unroll 4
        for (int j = 0; j < NUM_ATOMS; j++) {
            float p = my_in[j];
            float z = fmaf(delta, (float)j, V_MINF);
            float v = fminf(fmaxf(fmaf(slope, z, r), V_MINF), V_MAXF);
            float b = (v - V_MINF) * inv_delta;          // in [0, 50] exactly
            float lf = floorf(b);
            int l = (int)lf;
            float wu = b - lf;                            // 0 exactly when b integral
            if (l != cur) {                               // advance window by exactly 1
                my_out[cur] = a0;
                a0 = a1;
                a1 = 0.0f;
                cur = l;
            }
            a0 = fmaf(1.0f - wu, p, a0);
            a1 = fmaf(wu, p, a1);
        }

        // flush tail window
        my_out[cur] = a0;
        if (cur + 1 < NUM_ATOMS) my_out[cur + 1] = a1;
        // zero-fill tail bins (cur+1, 50]
        for (int i = cur + 2; i < NUM_ATOMS; i++) my_out[i] = 0.0f;
    }

    __syncthreads();

    // -------- cooperative coalesced store of the output tile --------
    float* gout = out + block_base;
    #pragma unroll
    for (int i = 0; i < NUM_ATOMS; i++) {
        int idx = i * THREADS + tid;
        if (block_base + idx < total_elems) gout[idx] = out_s[idx];
    }
}

extern "C" void kernel_launch(void* const* d_in, const int* in_sizes, int n_in,
                              void* d_out, int out_size)
{
    const float* reward   = (const float*)d_in[0];
    const float* probs    = (const float*)d_in[1];
    const float* not_done = (const float*)d_in[2];
    float* out = (float*)d_out;

    const int rows = in_sizes[0];  // reward element count == batch size
    const int blocks = (rows + ROWS_PER_BLOCK - 1) / ROWS_PER_BLOCK;
    const int smem_bytes = 2 * ROWS_PER_BLOCK * NUM_ATOMS * (int)sizeof(float);

    cudaFuncSetAttribute(c51_proj_kernel,
                         cudaFuncAttributeMaxDynamicSharedMemorySize, smem_bytes);

    c51_proj_kernel<<<blocks, THREADS, smem_bytes>>>(reward, probs, not_done, out, rows);
}

// round 6
// speedup vs baseline: 1.0554x; 1.0554x over previous
#include <cuda_runtime.h>

// CategoricalProjection (C51): rows=524288, NUM_ATOMS=51
// in: reward[rows], probs[rows*51], not_done[rows]  out: new_probs[rows*51]
//
// Single shared buffer, in-place streaming projection.
// b_j = clip(c + slope*j, 0, 50), slope = 0.99*nd, c = 2.5*r + 25 - 25*slope.
// floor(b_j) is monotone, advances by <=1 per atom -> 2-register window scatter.
// Direction (forward j=0..50 / reverse j=50..0) chosen per row so in-place
// writes never clobber unread inputs:
//   forward safe  iff c < 1.99   (write idx l_{j-1} <= j)
//   reverse safe  iff c >= -1.49 (write idx l_{j+1}+1 >= j)
// threshold 1.5 satisfies both.

#define NUM_ATOMS 51
#define THREADS 256
#define ROWS_PER_BLOCK 256
#define TILE_FLOATS (ROWS_PER_BLOCK * NUM_ATOMS)       // 13056
#define TILE_F4 (TILE_FLOATS / 4)                      // 3264
#define F4_ITERS ((TILE_F4 + THREADS - 1) / THREADS)   // 13
#define SMEM_FLOATS (TILE_FLOATS + THREADS)            // + per-thread dummy slot

__global__ __launch_bounds__(THREADS, 4)
void c51_proj_kernel(const float* __restrict__ reward,
                     const float* __restrict__ probs,
                     const float* __restrict__ not_done,
                     float* __restrict__ out,
                     int rows)
{
    extern __shared__ float tile[];   // [TILE_FLOATS] data + [THREADS] dummy
    const int tid = threadIdx.x;
    const long long base_f  = (long long)blockIdx.x * TILE_FLOATS;
    const long long total_f = (long long)rows * NUM_ATOMS;

    const int row = blockIdx.x * ROWS_PER_BLOCK + tid;
    float r = 0.0f, ndv = 0.0f;
    if (row < rows) { r = reward[row]; ndv = not_done[row]; }

    // ---- coalesced vectorized tile load (13 LDG.128 in flight) ----
    {
        const float4* g4 = (const float4*)(probs + base_f);
        float4* s4 = (float4*)tile;
        #pragma unroll
        for (int i = 0; i < F4_ITERS; i++) {
            int idx = i * THREADS + tid;
            if (idx < TILE_F4 && base_f + 4LL * idx < total_f)
                s4[idx] = g4[idx];
        }
    }
    __syncthreads();

    if (row < rows) {
        const float slope = 0.99f * ndv;                               // 0 or 0.99
        const float c = fmaf(2.5f, r, fmaf(-25.0f, slope, 25.0f));     // b_0 unclipped
        const bool fwd = (c < 1.5f);
        float* my = tile + tid * NUM_ATOMS;
        const int rowbase = tid * NUM_ATOMS;
        const int dummy = TILE_FLOATS + tid;

        // window init at first processed atom
        const float jf_first = fwd ? 0.0f : 50.0f;
        float bfirst = fminf(fmaxf(fmaf(slope, jf_first, c), 0.0f), 50.0f);
        int l_prev = (int)bfirst;          // b >= 0 -> trunc == floor
        float a0 = 0.0f, a1 = 0.0f;

        // branchless streaming scatter (store redirected to dummy when idle)
        #pragma unroll
        for (int k = 0; k < NUM_ATOMS; k++) {
            const int   j  = fwd ? k : (NUM_ATOMS - 1 - k);
            const float jf = fwd ? (float)k : (float)(NUM_ATOMS - 1 - k);
            float p = my[j];
            float b = fminf(fmaxf(fmaf(slope, jf, c), 0.0f), 50.0f);
            int   l = (int)b;
            float w = b - (float)l;                 // 0 exactly when b integral
            bool adv = (l != l_prev);
            int   widx = fwd ? l_prev : (l_prev + 1);
            float wval = fwd ? a0 : a1;
            int sidx = (adv && widx < NUM_ATOMS) ? (rowbase + widx) : dummy;
            tile[sidx] = wval;
            float na0 = adv ? (fwd ? a1 : 0.0f) : a0;
            float na1 = adv ? (fwd ? 0.0f : a0) : a1;
            a0 = fmaf(1.0f - w, p, na0);
            a1 = fmaf(w, p, na1);
            l_prev = l;
        }

        // flush final window
        my[l_prev] = a0;
        if (l_prev + 1 < NUM_ATOMS) my[l_prev + 1] = a1;

        // zero-fill untouched bins [0, lo) and (hi, 50]
        float bA = fminf(fmaxf(c, 0.0f), 50.0f);                       // b at j=0
        float bZ = fminf(fmaxf(fmaf(slope, 50.0f, c), 0.0f), 50.0f);   // b at j=50
        int lo = (int)bA;
        int hi = (int)bZ + 1;
        for (int i = 0; i < lo; i++)              my[i] = 0.0f;
        for (int i = hi + 1; i < NUM_ATOMS; i++)  my[i] = 0.0f;
    }
    __syncthreads();

    // ---- coalesced vectorized tile store ----
    {
        const float4* s4 = (const float4*)tile;
        float4* g4 = (float4*)(out + base_f);
        #pragma unroll
        for (int i = 0; i < F4_ITERS; i++) {
            int idx = i * THREADS + tid;
            if (idx < TILE_F4 && base_f + 4LL * idx < total_f)
                g4[idx] = s4[idx];
        }
    }
}

extern "C" void kernel_launch(void* const* d_in, const int* in_sizes, int n_in,
                              void* d_out, int out_size)
{
    const float* reward   = (const float*)d_in[0];
    const float* probs    = (const float*)d_in[1];
    const float* not_done = (const float*)d_in[2];
    float* out = (float*)d_out;

    const int rows = in_sizes[0];
    const int blocks = (rows + ROWS_PER_BLOCK - 1) / ROWS_PER_BLOCK;
    const int smem_bytes = SMEM_FLOATS * (int)sizeof(float);

    cudaFuncSetAttribute(c51_proj_kernel,
                         cudaFuncAttributeMaxDynamicSharedMemorySize, smem_bytes);

    c51_proj_kernel<<<blocks, THREADS, smem_bytes>>>(reward, probs, not_done, out, rows);
}

// round 8
// speedup vs baseline: 1.5540x; 1.4724x over previous
#include <cuda_runtime.h>

// CategoricalProjection (C51): rows=524288, NUM_ATOMS=51
// b_j = clamp(c + slope*j, 0, 50), slope = 0.99*nd, c = 2.5*r + 25 - 25*slope.
//
// slope==0  : delta output — out[l] = (1-w)*sum(p), out[l+1] = w*sum(p).
// slope==.99: forward streaming 2-register window scatter, in-place in smem.
//   Reflection trick: processing the row reversed == same forward loop with
//   c_eff = 0.5 - c (b' = 50-b => l' = 49-l, w' = 1-w; split maps exactly,
//   including integral-b edge). Choose fwd iff c < 1  =>  c_eff < 1 always
//   => first bin is 0 (no head fill), and in-place writes trail reads.

#define NUM_ATOMS 51
#define THREADS 256
#define ROWS_PER_BLOCK 256
#define TILE_FLOATS (ROWS_PER_BLOCK * NUM_ATOMS)       // 13056
#define TILE_F4 (TILE_FLOATS / 4)                      // 3264
#define F4_ITERS ((TILE_F4 + THREADS - 1) / THREADS)   // 13

__global__ __launch_bounds__(THREADS, 4)
void c51_proj_kernel(const float* __restrict__ reward,
                     const float* __restrict__ probs,
                     const float* __restrict__ not_done,
                     float* __restrict__ out,
                     int rows)
{
    extern __shared__ float tile[];   // [TILE_FLOATS], in-place projection
    const int tid = threadIdx.x;
    const long long base_f  = (long long)blockIdx.x * TILE_FLOATS;
    const long long total_f = (long long)rows * NUM_ATOMS;

    const int row = blockIdx.x * ROWS_PER_BLOCK + tid;
    float r = 0.0f, ndv = 0.0f;
    if (row < rows) { r = reward[row]; ndv = not_done[row]; }

    // ---- coalesced vectorized tile load ----
    {
        const float4* g4 = (const float4*)(probs + base_f);
        float4* s4 = (float4*)tile;
        #pragma unroll
        for (int i = 0; i < F4_ITERS; i++) {
            int idx = i * THREADS + tid;
            if (idx < TILE_F4 && base_f + 4LL * idx < total_f)
                s4[idx] = g4[idx];
        }
    }
    __syncthreads();

    if (row < rows) {
        const float slope = 0.99f * ndv;                            // 0 or 0.99
        const float c = fmaf(2.5f, r, fmaf(-25.0f, slope, 25.0f));  // unclipped b_0
        float* my = tile + tid * NUM_ATOMS;

        if (slope == 0.0f) {
            // ---- delta path: whole row collapses to one fractional bin ----
            float s0 = 0.f, s1 = 0.f, s2 = 0.f, s3 = 0.f;
            #pragma unroll
            for (int i = 0; i < 48; i += 4) {
                s0 += my[i]; s1 += my[i+1]; s2 += my[i+2]; s3 += my[i+3];
            }
            float S = (s0 + s1) + (s2 + s3) + my[48] + my[49] + my[50];
            float bv = fminf(fmaxf(c, 0.0f), 50.0f);
            float lf = floorf(bv);
            float w  = bv - lf;
            int   l  = (int)lf;
            #pragma unroll
            for (int i = 0; i < NUM_ATOMS; i++) my[i] = 0.0f;   // static addrs
            my[l] = (1.0f - w) * S;
            if (l < NUM_ATOMS - 1) my[l + 1] = w * S;
        } else {
            // ---- streaming path, unified direction via reflection ----
            const bool fwd = (c < 1.0f);
            const float ce = fwd ? c : (0.5f - c);     // effective offset, < 1
            const int   ds = fwd ? 1 : -1;
            const float* sp = my + (fwd ? 0 : 50);     // source cursor
            int dcur = fwd ? 0 : 50;                   // dest bin (actual coords)
            float lfp = 0.0f;                          // floor(b_0) == 0 always
            float a0 = 0.0f, a1 = 0.0f;

            #pragma unroll
            for (int k = 0; k < NUM_ATOMS; k++) {
                float p = *sp; sp += ds;
                float b = fminf(fmaxf(fmaf(slope, (float)k, ce), 0.0f), 50.0f);
                float lf = floorf(b);
                float w  = b - lf;
                bool adv = (lf != lfp);
                a0   = adv ? a1 : a0;
                a1   = adv ? 0.0f : a1;
                dcur = adv ? dcur + ds : dcur;
                a0 = fmaf(1.0f - w, p, a0);
                a1 = fmaf(w, p, a1);
                my[dcur] = a0;        // unconditional; rewrites until advance
                lfp = lf;
            }

            int lfinal = (int)lfp;                     // single F2I per row
            if (lfinal < NUM_ATOMS - 1) my[dcur + ds] = a1;
            // tail zeros: effective bins [lfinal+2, 50]
            int cnt = (NUM_ATOMS - 2) - lfinal;        // 49 - lfinal
            int za = dcur + 2 * ds;
            for (int i = 0; i < cnt; i++) { my[za] = 0.0f; za += ds; }
        }
    }
    __syncthreads();

    // ---- coalesced vectorized tile store ----
    {
        const float4* s4 = (const float4*)tile;
        float4* g4 = (float4*)(out + base_f);
        #pragma unroll
        for (int i = 0; i < F4_ITERS; i++) {
            int idx = i * THREADS + tid;
            if (idx < TILE_F4 && base_f + 4LL * idx < total_f)
                g4[idx] = s4[idx];
        }
    }
}

extern "C" void kernel_launch(void* const* d_in, const int* in_sizes, int n_in,
                              void* d_out, int out_size)
{
    const float* reward   = (const float*)d_in[0];
    const float* probs    = (const float*)d_in[1];
    const float* not_done = (const float*)d_in[2];
    float* outp = (float*)d_out;

    const int rows = in_sizes[0];
    const int blocks = (rows + ROWS_PER_BLOCK - 1) / ROWS_PER_BLOCK;
    const int smem_bytes = TILE_FLOATS * (int)sizeof(float);

    cudaFuncSetAttribute(c51_proj_kernel,
                         cudaFuncAttributeMaxDynamicSharedMemorySize, smem_bytes);

    c51_proj_kernel<<<blocks, THREADS, smem_bytes>>>(reward, probs, not_done, outp, rows);
}